// round 7
// baseline (speedup 1.0000x reference)
#include <cuda_runtime.h>

#define NN 2048
#define LOG2F_ 0.69314718055994530942f

typedef unsigned long long ull;

// Scratch (__device__ globals; no cudaMalloc allowed)
__device__ __align__(16) float g_M1T[32 * NN];   // [u][n] averaged em1, transposed
__device__ __align__(16) float g_M2[NN * 32];    // [n][u] averaged em2

// ---- packed f32x2 helpers (FFMA2 only reachable via PTX fma.rn.f32x2) ----
__device__ __forceinline__ ull pack2(float x, float y) {
    ull r;
    asm("mov.b64 %0, {%1, %2};" : "=l"(r) : "r"(__float_as_uint(x)), "r"(__float_as_uint(y)));
    return r;
}
__device__ __forceinline__ void unpack2(ull v, float& x, float& y) {
    unsigned lo, hi;
    asm("mov.b64 {%0, %1}, %2;" : "=r"(lo), "=r"(hi) : "l"(v));
    x = __uint_as_float(lo); y = __uint_as_float(hi);
}
__device__ __forceinline__ ull ffma2(ull a, ull b, ull c) {
    ull d;
    asm("fma.rn.f32x2 %0, %1, %2, %3;" : "=l"(d) : "l"(a), "l"(b), "l"(c));
    return d;
}

// stable softplus(x) = max(x,0) + log(1 + exp(-|x|))
__device__ __forceinline__ float softplus_f(float x) {
    float a = fabsf(x);
    float l = __logf(1.f + __expf(-a));
    return fmaxf(x, 0.f) + l;
}

// ---------------------------------------------------------------------------
// Kernel 1 (v4): embeddings + leaky_relu + agent-mean.
// K-pair vectorization: weights pre-paired along K in smem (sP[k2][u] holds
// (w[2k2][u], w[2k2+1][u])), input K-pairs come free from LDG.128 viewed as
// ulonglong2 -> inner loop is LDG/LDS.128/FFMA2 only, zero packing MOVs.
// Grid 512 x 256thr; thread = (nl 0..3, kq 0..3, uh 0..15 -> units 2uh,2uh+1).
// K split x4 per sample; partials (linear in K) reduced via smem.
// ---------------------------------------------------------------------------
__global__ void __launch_bounds__(256) embed_kernel(
    const float* __restrict__ state, const float* __restrict__ action,
    const float* __restrict__ W1, const float* __restrict__ b1,
    const float* __restrict__ W2, const float* __restrict__ b2) {
    __shared__ __align__(16) ull sP1[64][32];        // 16 KB paired W1
    __shared__ __align__(16) ull sP2[32][32];        //  8 KB paired W2
    __shared__ float sb1[32], sb2[32];
    __shared__ __align__(8) float sp1[4][4][5][32];  // 10 KB [nl][kq][a][u]
    __shared__ __align__(8) float sp2[4][4][5][32];  // 10 KB

    const int tid = threadIdx.x;

    #pragma unroll
    for (int i = 0; i < 8; i++) {                    // build paired W1
        int idx = tid + i * 256;                     // 0..2047
        int k2 = idx >> 5, u = idx & 31;
        sP1[k2][u] = pack2(W1[k2 * 64 + u], W1[k2 * 64 + 32 + u]);
    }
    #pragma unroll
    for (int i = 0; i < 4; i++) {                    // build paired W2
        int idx = tid + i * 256;                     // 0..1023
        int k2 = idx >> 5, u = idx & 31;
        sP2[k2][u] = pack2(W2[k2 * 64 + u], W2[k2 * 64 + 32 + u]);
    }
    if (tid < 32) { sb1[tid] = b1[tid]; sb2[tid] = b2[tid]; }
    __syncthreads();

    const int nl = tid >> 6, kq = (tid >> 4) & 3, uh = tid & 15;
    const int n = blockIdx.x * 4 + nl;

    // ---------------- GEMM1 partial: K-quarter (32 of 128) ----------------
    {
        const float* base = state + (size_t)n * 640 + kq * 32;
        ull acc[5][2];
        #pragma unroll
        for (int a = 0; a < 5; a++) { acc[a][0] = 0ull; acc[a][1] = 0ull; }

        #pragma unroll
        for (int k4 = 0; k4 < 8; k4++) {
            ulonglong2 x[5];
            #pragma unroll
            for (int a = 0; a < 5; a++)
                x[a] = *(const ulonglong2*)(base + a * 128 + k4 * 4);
            const int k2 = kq * 16 + k4 * 2;
            ulonglong2 w0 = *(const ulonglong2*)&sP1[k2][2 * uh];      // units u0,u1 @ kpair k2
            ulonglong2 w1 = *(const ulonglong2*)&sP1[k2 + 1][2 * uh];  // @ kpair k2+1
            #pragma unroll
            for (int a = 0; a < 5; a++) {
                acc[a][0] = ffma2(x[a].x, w0.x, acc[a][0]);
                acc[a][0] = ffma2(x[a].y, w1.x, acc[a][0]);
                acc[a][1] = ffma2(x[a].x, w0.y, acc[a][1]);
                acc[a][1] = ffma2(x[a].y, w1.y, acc[a][1]);
            }
        }
        #pragma unroll
        for (int a = 0; a < 5; a++) {
            float x0, x1, y0, y1;
            unpack2(acc[a][0], x0, x1);
            unpack2(acc[a][1], y0, y1);
            *(float2*)&sp1[nl][kq][a][2 * uh] = make_float2(x0 + x1, y0 + y1);
        }
    }

    // ---------------- GEMM2 partial: K-quarter (16 of 64) ----------------
    {
        const float* base = action + (size_t)n * 320 + kq * 16;
        ull acc[5][2];
        #pragma unroll
        for (int a = 0; a < 5; a++) { acc[a][0] = 0ull; acc[a][1] = 0ull; }

        #pragma unroll
        for (int k4 = 0; k4 < 4; k4++) {
            ulonglong2 x[5];
            #pragma unroll
            for (int a = 0; a < 5; a++)
                x[a] = *(const ulonglong2*)(base + a * 64 + k4 * 4);
            const int k2 = kq * 8 + k4 * 2;
            ulonglong2 w0 = *(const ulonglong2*)&sP2[k2][2 * uh];
            ulonglong2 w1 = *(const ulonglong2*)&sP2[k2 + 1][2 * uh];
            #pragma unroll
            for (int a = 0; a < 5; a++) {
                acc[a][0] = ffma2(x[a].x, w0.x, acc[a][0]);
                acc[a][0] = ffma2(x[a].y, w1.x, acc[a][0]);
                acc[a][1] = ffma2(x[a].x, w0.y, acc[a][1]);
                acc[a][1] = ffma2(x[a].y, w1.y, acc[a][1]);
            }
        }
        #pragma unroll
        for (int a = 0; a < 5; a++) {
            float x0, x1, y0, y1;
            unpack2(acc[a][0], x0, x1);
            unpack2(acc[a][1], y0, y1);
            *(float2*)&sp2[nl][kq][a][2 * uh] = make_float2(x0 + x1, y0 + y1);
        }
    }

    __syncthreads();

    // ---------------- finalize: bias + leaky + agent-mean ----------------
    if (tid < 128) {
        {   // M1T: mapping chosen for semi-coalesced transposed store
            const int fu = tid >> 2, fnl = tid & 3;
            const int fn = blockIdx.x * 4 + fnl;
            float m = 0.f;
            #pragma unroll
            for (int a = 0; a < 5; a++) {
                float v = sb1[fu];
                #pragma unroll
                for (int q = 0; q < 4; q++) v += sp1[fnl][q][a][fu];
                m += (v > 0.f) ? v : 0.01f * v;      // leaky_relu(0.01)
            }
            g_M1T[fu * NN + fn] = 0.2f * m;
        }
        {   // M2: u-fastest mapping -> coalesced
            const int fnl = tid >> 5, fu = tid & 31;
            const int fn = blockIdx.x * 4 + fnl;
            float m = 0.f;
            #pragma unroll
            for (int a = 0; a < 5; a++) {
                float v = sb2[fu];
                #pragma unroll
                for (int q = 0; q < 4; q++) v += sp2[fnl][q][a][fu];
                m += (v > 0.f) ? v : 0.01f * v;
            }
            g_M2[fn * 32 + fu] = 0.2f * m;
        }
    }
}

// ---------------------------------------------------------------------------
// Kernel 2 (v2): fused GEMM (u[i,j]=M2[i].M1[j], K=32) + softplus row-sums +
// FINAL loss/MI (fin kernel merged). Grid 128 (one wave), block 256.
// Block owns 16 i-rows x ALL 2048 j (8 chunks of 256, double-buffered smem,
// LDG prefetch overlaps compute). A staged pre-DUPLICATED ((a,a) pairs) so the
// inner loop has zero packing MOVs: 3 LDS.128 + 8 FFMA2 per u-iter.
// Thread = (ti 0..3, tj 0..63): rows ti*4..+3, cols tj*4..+3 (j-pairs).
// ---------------------------------------------------------------------------
__global__ void __launch_bounds__(256) jsd_kernel(float* __restrict__ out) {
    __shared__ __align__(16) ull sA2[32][16];        // (a,a) dup pairs, 4 KB
    __shared__ __align__(16) float sB[2][32 * 256];  // 64 KB double buffer
    __shared__ float sdiag[16];
    __shared__ float swsum[8][4];

    const int tid = threadIdx.x;
    const int i0 = blockIdx.x * 16;
    const int ti = tid >> 6, tj = tid & 63;

    // stage A duplicated: sA2[u][ii] = (M2[i0+ii][u], same)
    for (int t = tid; t < 512; t += 256) {
        int u = t >> 4, ii = t & 15;
        float v = g_M2[(i0 + ii) * 32 + u];
        sA2[u][ii] = pack2(v, v);
    }

    // preload chunk 0
    float4 st[8];
    #pragma unroll
    for (int t = 0; t < 8; t++) {
        int idx = tid + t * 256;                     // 0..2047
        int u = idx >> 6, f = (idx & 63) * 4;
        st[t] = *(const float4*)&g_M1T[u * NN + f];
    }
    #pragma unroll
    for (int t = 0; t < 8; t++) {
        int idx = tid + t * 256;
        int u = idx >> 6, f = (idx & 63) * 4;
        *(float4*)&sB[0][u * 256 + f] = st[t];
    }
    __syncthreads();

    float rowsum[4] = {0.f, 0.f, 0.f, 0.f};
    const int dc_chunk = i0 >> 8;                    // chunk holding the diagonal

    for (int c = 0; c < 8; c++) {
        // prefetch next chunk into registers (overlaps compute below)
        if (c < 7) {
            const int j0n = (c + 1) * 256;
            #pragma unroll
            for (int t = 0; t < 8; t++) {
                int idx = tid + t * 256;
                int u = idx >> 6, f = (idx & 63) * 4;
                st[t] = *(const float4*)&g_M1T[u * NN + j0n + f];
            }
        }

        const float* Bc = sB[c & 1];
        ull acc[4][2];
        #pragma unroll
        for (int i = 0; i < 4; i++) { acc[i][0] = 0ull; acc[i][1] = 0ull; }

        #pragma unroll 8
        for (int u = 0; u < 32; u++) {
            ulonglong2 ad0 = *(const ulonglong2*)&sA2[u][ti * 4];      // rows 0,1 dup
            ulonglong2 ad1 = *(const ulonglong2*)&sA2[u][ti * 4 + 2];  // rows 2,3 dup
            ulonglong2 bp  = *(const ulonglong2*)&Bc[u * 256 + tj * 4]; // j-pairs
            acc[0][0] = ffma2(ad0.x, bp.x, acc[0][0]);
            acc[0][1] = ffma2(ad0.x, bp.y, acc[0][1]);
            acc[1][0] = ffma2(ad0.y, bp.x, acc[1][0]);
            acc[1][1] = ffma2(ad0.y, bp.y, acc[1][1]);
            acc[2][0] = ffma2(ad1.x, bp.x, acc[2][0]);
            acc[2][1] = ffma2(ad1.x, bp.y, acc[2][1]);
            acc[3][0] = ffma2(ad1.y, bp.x, acc[3][0]);
            acc[3][1] = ffma2(ad1.y, bp.y, acc[3][1]);
        }

        // epilogue: diag capture (only on the diagonal chunk) + softplus sums
        const int jbase = c * 256 + tj * 4;
        const bool isdc = (c == dc_chunk);
        #pragma unroll
        for (int i = 0; i < 4; i++) {
            float x0, x1, x2, x3;
            unpack2(acc[i][0], x0, x1);
            unpack2(acc[i][1], x2, x3);
            if (isdc) {
                int ig = i0 + ti * 4 + i;
                if (jbase     == ig) sdiag[ti * 4 + i] = x0;
                if (jbase + 1 == ig) sdiag[ti * 4 + i] = x1;
                if (jbase + 2 == ig) sdiag[ti * 4 + i] = x2;
                if (jbase + 3 == ig) sdiag[ti * 4 + i] = x3;
            }
            rowsum[i] += softplus_f(x0) + softplus_f(x1)
                       + softplus_f(x2) + softplus_f(x3);
        }

        // commit prefetched chunk to the other buffer
        if (c < 7) {
            #pragma unroll
            for (int t = 0; t < 8; t++) {
                int idx = tid + t * 256;
                int u = idx >> 6, f = (idx & 63) * 4;
                *(float4*)&sB[(c + 1) & 1][u * 256 + f] = st[t];
            }
        }
        __syncthreads();
    }

    // reduce rowsum across the 64 tj-threads sharing each i row
    const int lane = tid & 31, wid = tid >> 5;
    #pragma unroll
    for (int r = 0; r < 4; r++) {
        float v = rowsum[r];
        v += __shfl_down_sync(0xffffffffu, v, 16);
        v += __shfl_down_sync(0xffffffffu, v, 8);
        v += __shfl_down_sync(0xffffffffu, v, 4);
        v += __shfl_down_sync(0xffffffffu, v, 2);
        v += __shfl_down_sync(0xffffffffu, v, 1);
        if (lane == 0) swsum[wid][r] = v;
    }
    __syncthreads();

    // finalize loss/MI for this block's 16 rows
    if (tid < 16) {
        const int r = tid;
        const int w0 = (r >> 2) * 2;                 // warps 2*ti, 2*ti+1
        float tot = swsum[w0][r & 3] + swsum[w0 + 1][r & 3];  // incl. diag softplus
        float ud  = sdiag[r];
        float spd = softplus_f(ud);
        float Eneg = (tot - spd - 2047.f * LOG2F_) * (1.f / 2047.f);
        float Epos = LOG2F_ - spd + ud;              // = log2 - softplus(-u_ii)
        const int i = i0 + r;
        out[i]      = Eneg - Epos;                   // loss
        out[NN + i] = Epos;                          // MI
    }
}

extern "C" void kernel_launch(void* const* d_in, const int* in_sizes, int n_in,
                              void* d_out, int out_size) {
    const float* state  = (const float*)d_in[0];
    const float* action = (const float*)d_in[1];
    const float* W1     = (const float*)d_in[2];
    const float* b1     = (const float*)d_in[3];
    const float* W2     = (const float*)d_in[4];
    const float* b2     = (const float*)d_in[5];
    float* out = (float*)d_out;

    embed_kernel<<<NN / 4, 256>>>(state, action, W1, b1, W2, b2);
    jsd_kernel<<<NN / 16, 256>>>(out);
}

// round 8
// speedup vs baseline: 1.2086x; 1.2086x over previous
#include <cuda_runtime.h>

#define NN 2048
#define LOG2F_ 0.69314718055994530942f

typedef unsigned long long ull;

// Scratch (__device__ globals; no cudaMalloc allowed)
__device__ __align__(16) float g_M1T[32 * NN];   // [u][n] averaged em1, transposed
__device__ __align__(16) ull   g_A2[32 * NN];    // [u][n] averaged em2, DUP pairs (v,v)
__device__ float g_partial[4 * NN];              // softplus row-sums per j-quarter
__device__ float g_diag[NN];                     // raw u_ii

// ---- packed f32x2 helpers (FFMA2 only reachable via PTX fma.rn.f32x2) ----
__device__ __forceinline__ ull pack2(float x, float y) {
    ull r;
    asm("mov.b64 %0, {%1, %2};" : "=l"(r) : "r"(__float_as_uint(x)), "r"(__float_as_uint(y)));
    return r;
}
__device__ __forceinline__ void unpack2(ull v, float& x, float& y) {
    unsigned lo, hi;
    asm("mov.b64 {%0, %1}, %2;" : "=r"(lo), "=r"(hi) : "l"(v));
    x = __uint_as_float(lo); y = __uint_as_float(hi);
}
__device__ __forceinline__ ull ffma2(ull a, ull b, ull c) {
    ull d;
    asm("fma.rn.f32x2 %0, %1, %2, %3;" : "=l"(d) : "l"(a), "l"(b), "l"(c));
    return d;
}

// stable softplus(x) = max(x,0) + log(1 + exp(-|x|))
__device__ __forceinline__ float softplus_f(float x) {
    float a = fabsf(x);
    float l = __logf(1.f + __expf(-a));
    return fmaxf(x, 0.f) + l;
}

// ---------------------------------------------------------------------------
// Kernel 1 (v4b): embeddings + leaky_relu + agent-mean.
// Same as R3/R7 v4 (best measured embed), except M2 is emitted pre-duplicated
// into g_A2[u][n] = (v,v) with n-fast store mapping, so jsd stages A with
// coalesced LDG.64 + conflict-free STS and zero packing MOVs.
// ---------------------------------------------------------------------------
__global__ void __launch_bounds__(256) embed_kernel(
    const float* __restrict__ state, const float* __restrict__ action,
    const float* __restrict__ W1, const float* __restrict__ b1,
    const float* __restrict__ W2, const float* __restrict__ b2) {
    __shared__ __align__(16) ull sP1[64][32];        // 16 KB paired W1
    __shared__ __align__(16) ull sP2[32][32];        //  8 KB paired W2
    __shared__ float sb1[32], sb2[32];
    __shared__ __align__(8) float sp1[4][4][5][32];  // 10 KB [nl][kq][a][u]
    __shared__ __align__(8) float sp2[4][4][5][32];  // 10 KB

    const int tid = threadIdx.x;

    #pragma unroll
    for (int i = 0; i < 8; i++) {                    // build paired W1
        int idx = tid + i * 256;                     // 0..2047
        int k2 = idx >> 5, u = idx & 31;
        sP1[k2][u] = pack2(W1[k2 * 64 + u], W1[k2 * 64 + 32 + u]);
    }
    #pragma unroll
    for (int i = 0; i < 4; i++) {                    // build paired W2
        int idx = tid + i * 256;                     // 0..1023
        int k2 = idx >> 5, u = idx & 31;
        sP2[k2][u] = pack2(W2[k2 * 64 + u], W2[k2 * 64 + 32 + u]);
    }
    if (tid < 32) { sb1[tid] = b1[tid]; sb2[tid] = b2[tid]; }
    __syncthreads();

    const int nl = tid >> 6, kq = (tid >> 4) & 3, uh = tid & 15;
    const int n = blockIdx.x * 4 + nl;

    // ---------------- GEMM1 partial: K-quarter (32 of 128) ----------------
    {
        const float* base = state + (size_t)n * 640 + kq * 32;
        ull acc[5][2];
        #pragma unroll
        for (int a = 0; a < 5; a++) { acc[a][0] = 0ull; acc[a][1] = 0ull; }

        #pragma unroll
        for (int k4 = 0; k4 < 8; k4++) {
            ulonglong2 x[5];
            #pragma unroll
            for (int a = 0; a < 5; a++)
                x[a] = *(const ulonglong2*)(base + a * 128 + k4 * 4);
            const int k2 = kq * 16 + k4 * 2;
            ulonglong2 w0 = *(const ulonglong2*)&sP1[k2][2 * uh];
            ulonglong2 w1 = *(const ulonglong2*)&sP1[k2 + 1][2 * uh];
            #pragma unroll
            for (int a = 0; a < 5; a++) {
                acc[a][0] = ffma2(x[a].x, w0.x, acc[a][0]);
                acc[a][0] = ffma2(x[a].y, w1.x, acc[a][0]);
                acc[a][1] = ffma2(x[a].x, w0.y, acc[a][1]);
                acc[a][1] = ffma2(x[a].y, w1.y, acc[a][1]);
            }
        }
        #pragma unroll
        for (int a = 0; a < 5; a++) {
            float x0, x1, y0, y1;
            unpack2(acc[a][0], x0, x1);
            unpack2(acc[a][1], y0, y1);
            *(float2*)&sp1[nl][kq][a][2 * uh] = make_float2(x0 + x1, y0 + y1);
        }
    }

    // ---------------- GEMM2 partial: K-quarter (16 of 64) ----------------
    {
        const float* base = action + (size_t)n * 320 + kq * 16;
        ull acc[5][2];
        #pragma unroll
        for (int a = 0; a < 5; a++) { acc[a][0] = 0ull; acc[a][1] = 0ull; }

        #pragma unroll
        for (int k4 = 0; k4 < 4; k4++) {
            ulonglong2 x[5];
            #pragma unroll
            for (int a = 0; a < 5; a++)
                x[a] = *(const ulonglong2*)(base + a * 64 + k4 * 4);
            const int k2 = kq * 8 + k4 * 2;
            ulonglong2 w0 = *(const ulonglong2*)&sP2[k2][2 * uh];
            ulonglong2 w1 = *(const ulonglong2*)&sP2[k2 + 1][2 * uh];
            #pragma unroll
            for (int a = 0; a < 5; a++) {
                acc[a][0] = ffma2(x[a].x, w0.x, acc[a][0]);
                acc[a][0] = ffma2(x[a].y, w1.x, acc[a][0]);
                acc[a][1] = ffma2(x[a].x, w0.y, acc[a][1]);
                acc[a][1] = ffma2(x[a].y, w1.y, acc[a][1]);
            }
        }
        #pragma unroll
        for (int a = 0; a < 5; a++) {
            float x0, x1, y0, y1;
            unpack2(acc[a][0], x0, x1);
            unpack2(acc[a][1], y0, y1);
            *(float2*)&sp2[nl][kq][a][2 * uh] = make_float2(x0 + x1, y0 + y1);
        }
    }

    __syncthreads();

    // ---------------- finalize: bias + leaky + agent-mean ----------------
    // n-fast mapping: quad of threads writes 4 consecutive n for one u.
    if (tid < 128) {
        const int fu = tid >> 2, fnl = tid & 3;
        const int fn = blockIdx.x * 4 + fnl;

        float m1 = 0.f;
        #pragma unroll
        for (int a = 0; a < 5; a++) {
            float v = sb1[fu];
            #pragma unroll
            for (int q = 0; q < 4; q++) v += sp1[fnl][q][a][fu];
            m1 += (v > 0.f) ? v : 0.01f * v;         // leaky_relu(0.01)
        }
        g_M1T[fu * NN + fn] = 0.2f * m1;

        float m2 = 0.f;
        #pragma unroll
        for (int a = 0; a < 5; a++) {
            float v = sb2[fu];
            #pragma unroll
            for (int q = 0; q < 4; q++) v += sp2[fnl][q][a][fu];
            m2 += (v > 0.f) ? v : 0.01f * v;
        }
        float s2 = 0.2f * m2;
        g_A2[fu * NN + fn] = pack2(s2, s2);          // pre-duplicated pair
    }
}

// ---------------------------------------------------------------------------
// Kernel 2 (v3): fused GEMM (u[i,j]=M2[i].M1[j], K=32) + softplus row-sums.
// Grid 256 = 64 i-tiles(32 rows) x 4 j-quarters(512 cols); single wave,
// ~2 blocks/SM. Warp = 4 i-rows (A loads warp-broadcast). Thread tile
// 4i x 8j: cols {tj*4..+3} and {128+tj*4..+3} of each 256-col chunk
// (both contiguous float4 -> conflict-free LDS.128).
// Per u-iter: 2 bcast LDS + 2 LDS.128 + 16 FFMA2.
// ---------------------------------------------------------------------------
__global__ void __launch_bounds__(256) jsd_kernel() {
    __shared__ __align__(16) ull sA2[32][32];        // 8 KB [u][ii] dup pairs
    __shared__ __align__(16) float sB[32][256];      // 32 KB chunk buffer

    const int tid = threadIdx.x;
    const int ib = blockIdx.x >> 2, q = blockIdx.x & 3;
    const int i0 = ib * 32, jq = q * 512;
    const int ti = tid >> 5, tj = tid & 31;          // warp id = ti

    // stage A (coalesced LDG.64, conflict-free STS)
    #pragma unroll
    for (int t = 0; t < 4; t++) {
        int idx = tid + t * 256;                     // 0..1023
        int u = idx >> 5, ii = idx & 31;
        sA2[u][ii] = g_A2[u * NN + i0 + ii];
    }
    // stage B chunk 0 (coalesced float4)
    float4 st[8];
    #pragma unroll
    for (int t = 0; t < 8; t++) {
        int idx = tid + t * 256;                     // 0..2047
        int u = idx >> 6, f = (idx & 63) * 4;
        st[t] = *(const float4*)&g_M1T[u * NN + jq + f];
    }
    #pragma unroll
    for (int t = 0; t < 8; t++) {
        int idx = tid + t * 256;
        int u = idx >> 6, f = (idx & 63) * 4;
        *(float4*)&sB[u][f] = st[t];
    }
    __syncthreads();

    float rowsum[4] = {0.f, 0.f, 0.f, 0.f};
    const bool qmatch = (q == (i0 >> 9));
    const int dc = (i0 & 511) >> 8;                  // diag chunk within quarter

    #pragma unroll
    for (int c = 0; c < 2; c++) {
        if (c == 0) {                                // prefetch chunk 1
            #pragma unroll
            for (int t = 0; t < 8; t++) {
                int idx = tid + t * 256;
                int u = idx >> 6, f = (idx & 63) * 4;
                st[t] = *(const float4*)&g_M1T[u * NN + jq + 256 + f];
            }
        }

        ull acc[4][4];
        #pragma unroll
        for (int r = 0; r < 4; r++)
            #pragma unroll
            for (int p = 0; p < 4; p++) acc[r][p] = 0ull;

        #pragma unroll 8
        for (int u = 0; u < 32; u++) {
            ulonglong2 ad0 = *(const ulonglong2*)&sA2[u][ti * 4];      // rows 0,1 dup
            ulonglong2 ad1 = *(const ulonglong2*)&sA2[u][ti * 4 + 2];  // rows 2,3 dup
            ulonglong2 b0  = *(const ulonglong2*)&sB[u][tj * 4];       // cols tj*4..+3
            ulonglong2 b1  = *(const ulonglong2*)&sB[u][128 + tj * 4]; // cols 128+tj*4..+3
            acc[0][0] = ffma2(ad0.x, b0.x, acc[0][0]);
            acc[0][1] = ffma2(ad0.x, b0.y, acc[0][1]);
            acc[0][2] = ffma2(ad0.x, b1.x, acc[0][2]);
            acc[0][3] = ffma2(ad0.x, b1.y, acc[0][3]);
            acc[1][0] = ffma2(ad0.y, b0.x, acc[1][0]);
            acc[1][1] = ffma2(ad0.y, b0.y, acc[1][1]);
            acc[1][2] = ffma2(ad0.y, b1.x, acc[1][2]);
            acc[1][3] = ffma2(ad0.y, b1.y, acc[1][3]);
            acc[2][0] = ffma2(ad1.x, b0.x, acc[2][0]);
            acc[2][1] = ffma2(ad1.x, b0.y, acc[2][1]);
            acc[2][2] = ffma2(ad1.x, b1.x, acc[2][2]);
            acc[2][3] = ffma2(ad1.x, b1.y, acc[2][3]);
            acc[3][0] = ffma2(ad1.y, b0.x, acc[3][0]);
            acc[3][1] = ffma2(ad1.y, b0.y, acc[3][1]);
            acc[3][2] = ffma2(ad1.y, b1.x, acc[3][2]);
            acc[3][3] = ffma2(ad1.y, b1.y, acc[3][3]);
        }

        // epilogue: diag capture + softplus row sums
        const bool isdc = qmatch && (c == dc);
        const int cbase = jq + c * 256;
        #pragma unroll
        for (int r = 0; r < 4; r++) {
            const int ig = i0 + ti * 4 + r;
            float s = 0.f;
            #pragma unroll
            for (int p = 0; p < 4; p++) {
                float x0, x1;
                unpack2(acc[r][p], x0, x1);
                if (isdc) {
                    int col = cbase + ((p < 2) ? (tj * 4 + p * 2)
                                               : (128 + tj * 4 + (p - 2) * 2));
                    if (col == ig)     g_diag[ig] = x0;   // single writer
                    if (col + 1 == ig) g_diag[ig] = x1;
                }
                s += softplus_f(x0) + softplus_f(x1);
            }
            rowsum[r] += s;
        }

        if (c == 0) {
            __syncthreads();                         // done reading sB chunk 0
            #pragma unroll
            for (int t = 0; t < 8; t++) {
                int idx = tid + t * 256;
                int u = idx >> 6, f = (idx & 63) * 4;
                *(float4*)&sB[u][f] = st[t];
            }
            __syncthreads();
        }
    }

    // rows live entirely within one warp: shfl-reduce across tj lanes
    #pragma unroll
    for (int r = 0; r < 4; r++) {
        float v = rowsum[r];
        v += __shfl_down_sync(0xffffffffu, v, 16);
        v += __shfl_down_sync(0xffffffffu, v, 8);
        v += __shfl_down_sync(0xffffffffu, v, 4);
        v += __shfl_down_sync(0xffffffffu, v, 2);
        v += __shfl_down_sync(0xffffffffu, v, 1);
        if (tj == 0) g_partial[q * NN + i0 + ti * 4 + r] = v;
    }
}

// ---------------------------------------------------------------------------
// Kernel 3: combine 4 quarter-partials, finalize loss/MI.
// ---------------------------------------------------------------------------
__global__ void __launch_bounds__(256) fin_kernel(float* __restrict__ out) {
    int i = blockIdx.x * 256 + threadIdx.x;
    float tot = g_partial[i] + g_partial[NN + i]
              + g_partial[2 * NN + i] + g_partial[3 * NN + i];  // incl. diag sp
    float ud  = g_diag[i];
    float spd = softplus_f(ud);
    float Eneg = (tot - spd - 2047.f * LOG2F_) * (1.f / 2047.f);
    float Epos = LOG2F_ - spd + ud;                  // = log2 - softplus(-u_ii)
    out[i]      = Eneg - Epos;                       // loss
    out[NN + i] = Epos;                              // MI
}

extern "C" void kernel_launch(void* const* d_in, const int* in_sizes, int n_in,
                              void* d_out, int out_size) {
    const float* state  = (const float*)d_in[0];
    const float* action = (const float*)d_in[1];
    const float* W1     = (const float*)d_in[2];
    const float* b1     = (const float*)d_in[3];
    const float* W2     = (const float*)d_in[4];
    const float* b2     = (const float*)d_in[5];
    float* out = (float*)d_out;

    embed_kernel<<<NN / 4, 256>>>(state, action, W1, b1, W2, b2);
    jsd_kernel<<<256, 256>>>();
    fin_kernel<<<NN / 256, 256>>>(out);
}